// round 1
// baseline (speedup 1.0000x reference)
#include <cuda_runtime.h>
#include <cuda_bf16.h>

// Reference analysis: _encode_batch ignores x entirely and produces the basis
// state e_0 for every row. So overlap[i,j] = <e0|e0> = 1 and
// K = |overlap|^2 = all-ones [2048, 2048] float32.
// The whole problem is a 16.78 MB constant fill -> pure HBM-write bound.

__global__ void fill_ones_f4(float4* __restrict__ out, int n4) {
    int i = blockIdx.x * blockDim.x + threadIdx.x;
    if (i < n4) {
        out[i] = make_float4(1.0f, 1.0f, 1.0f, 1.0f);
    }
}

// Tail handler in case out_size is not a multiple of 4 (it is here: 4194304).
__global__ void fill_ones_tail(float* __restrict__ out, int start, int n) {
    int i = start + blockIdx.x * blockDim.x + threadIdx.x;
    if (i < n) out[i] = 1.0f;
}

extern "C" void kernel_launch(void* const* d_in, const int* in_sizes, int n_in,
                              void* d_out, int out_size) {
    (void)d_in; (void)in_sizes; (void)n_in;
    float* out = (float*)d_out;

    int n4 = out_size >> 2;            // number of float4 stores
    if (n4 > 0) {
        const int threads = 256;
        int blocks = (n4 + threads - 1) / threads;
        fill_ones_f4<<<blocks, threads>>>((float4*)out, n4);
    }
    int done = n4 << 2;
    int rem = out_size - done;
    if (rem > 0) {
        fill_ones_tail<<<1, 256>>>(out, done, out_size);
    }
}

// round 2
// speedup vs baseline: 1.0039x; 1.0039x over previous
#include <cuda_runtime.h>
#include <cuda_bf16.h>

// Output = all-ones [2048,2048] f32 (reference's encoder maps every sample to
// the e_0 basis state, so all pairwise fidelities are exactly 1).
// 16.78 MB fill; fits in L2 (126 MB) -> L2-write bound, floor ~1.4us.
// R1 lesson: 1 store/thread left the LSU queue empty (L2 at 26%). Now each
// thread issues 8 independent STG.128 (MLP=8), 8x fewer blocks.

#ifndef FILL_VPT
#define FILL_VPT 8   // float4 per thread
#endif

__global__ void fill_ones_f4x8(float4* __restrict__ out) {
    // Each block owns a contiguous slab of blockDim.x * FILL_VPT float4s.
    const float4 ones = make_float4(1.0f, 1.0f, 1.0f, 1.0f);
    float4* p = out + (size_t)blockIdx.x * (blockDim.x * FILL_VPT) + threadIdx.x;
#pragma unroll
    for (int i = 0; i < FILL_VPT; i++) {
        p[i * 256] = ones;          // blockDim.x == 256, compile-time stride
    }
}

// Generic fallback for any residual elements (not hit for out_size=4194304).
__global__ void fill_ones_tail(float* __restrict__ out, int start, int n) {
    int i = start + blockIdx.x * blockDim.x + threadIdx.x;
    if (i < n) out[i] = 1.0f;
}

extern "C" void kernel_launch(void* const* d_in, const int* in_sizes, int n_in,
                              void* d_out, int out_size) {
    (void)d_in; (void)in_sizes; (void)n_in;
    float* out = (float*)d_out;

    const int threads = 256;
    const int f4_per_block = threads * FILL_VPT;      // 2048 float4 = 32 KB
    int n4 = out_size >> 2;
    int full_blocks = n4 / f4_per_block;              // 512 for 1,048,576

    if (full_blocks > 0) {
        fill_ones_f4x8<<<full_blocks, threads>>>((float4*)out);
    }
    int done = full_blocks * f4_per_block * 4;
    int rem = out_size - done;
    if (rem > 0) {
        int blocks = (rem + threads - 1) / threads;
        fill_ones_tail<<<blocks, threads>>>(out, done, out_size);
    }
}